// round 4
// baseline (speedup 1.0000x reference)
#include <cuda_runtime.h>
#include <math.h>

#define T_STEPS   32768
#define N_NEUR    1024
#define FILT_LEN  200
#define THREADS   256
#define CHUNK     2048

#define LOG_DT_F      (-6.907755278982137f)
#define NOISE_SIGMA_F (0.2f)
#define FILT_DECAY_F  (0.05f)
#define INH_FACTOR_F  (0.8187307530779818f)
#define INH_INC_F     (3000.0f)

// scratch (no cudaMalloc allowed)
__device__ float g_thr[T_STEPS];
__device__ int   g_loc[T_STEPS];

// ---------------------------------------------------------------------------
// One block per time step t.
//  - computes noise[t] (200-tap FIR, tap per thread, tree reduce)
//  - computes logsumexp(inputs[t] + noise[t])  (bit-faithful structure:
//    max(x+c) == round(max(x)+c) by rounding monotonicity)
//  - computes spike location = count of prefix-sums < u * sumexp
//  - writes thr[t], loc[t], noise output, and zero-fills the out_spikes row
// ---------------------------------------------------------------------------
__global__ void __launch_bounds__(THREADS)
row_kernel(const float* __restrict__ inputs,
           const float* __restrict__ noise_rand,
           const float* __restrict__ u_mult,
           const float* __restrict__ rand_val,
           float* __restrict__ out)
{
    const int t    = blockIdx.x;
    const int tid  = threadIdx.x;
    const int lane = tid & 31;
    const int wid  = tid >> 5;
    const unsigned FULL = 0xffffffffu;

    __shared__ float s_max[8];
    __shared__ float s_ns[8];
    __shared__ float s_wsum[8];
    __shared__ int   s_cnt[8];
    __shared__ float s_b[2];   // [0]=noise c, [1]=m' = rowmax + c

    // --- load 4 input elements (vectorized) ---
    const float4 x4 =
        reinterpret_cast<const float4*>(inputs)[(size_t)t * (N_NEUR / 4) + tid];

    // --- noise tap: noise[t] = sum_j nr[t-j] * exp(-j*0.05) ---
    float prod = 0.0f;
    if (tid < FILT_LEN) {
        int idx = t - tid;
        if (idx >= 0) {
            float nr   = noise_rand[idx] * NOISE_SIGMA_F;
            float filt = expf(-((float)tid) * FILT_DECAY_F);
            prod = nr * filt;
        }
    }

    // --- joint warp reduce: row max + noise sum ---
    float lm = fmaxf(fmaxf(x4.x, x4.y), fmaxf(x4.z, x4.w));
    #pragma unroll
    for (int o = 16; o; o >>= 1) {
        lm   = fmaxf(lm, __shfl_xor_sync(FULL, lm, o));
        prod += __shfl_xor_sync(FULL, prod, o);
    }
    if (lane == 0) { s_max[wid] = lm; s_ns[wid] = prod; }
    __syncthreads();
    if (tid == 0) {
        float m = s_max[0], c = s_ns[0];
        #pragma unroll
        for (int i = 1; i < 8; i++) { m = fmaxf(m, s_max[i]); c += s_ns[i]; }
        s_b[0] = c;
        s_b[1] = m + c;     // m' for inputs+noise (monotone rounding)
    }
    __syncthreads();
    const float c  = s_b[0];
    const float mp = s_b[1];

    // --- exp((x + c) - m'), local inclusive prefix over 4 elements ---
    const float e0 = expf((x4.x + c) - mp);
    const float e1 = expf((x4.y + c) - mp);
    const float e2 = expf((x4.z + c) - mp);
    const float e3 = expf((x4.w + c) - mp);
    const float p0 = e0;
    const float p1 = p0 + e1;
    const float p2 = p1 + e2;
    const float p3 = p2 + e3;

    // --- block exclusive scan of per-thread totals (monotone prefix sums) ---
    float incl = p3;
    #pragma unroll
    for (int o = 1; o < 32; o <<= 1) {
        float n = __shfl_up_sync(FULL, incl, o);
        if (lane >= o) incl += n;
    }
    if (lane == 31) s_wsum[wid] = incl;
    __syncthreads();
    float warp_off = 0.0f, stot = 0.0f;
    {
        float acc = 0.0f;
        #pragma unroll
        for (int i = 0; i < 8; i++) {
            if (i == wid) warp_off = acc;
            acc += s_wsum[i];
        }
        stot = acc;
    }
    float excl = __shfl_up_sync(FULL, incl, 1);
    if (lane == 0) excl = 0.0f;
    const float base = warp_off + excl;

    // --- spike location: count of cumsum < u * sumexp ---
    const float us = u_mult[t] * stot;
    int cnt = (int)((base + p0) < us) + (int)((base + p1) < us)
            + (int)((base + p2) < us) + (int)((base + p3) < us);
    #pragma unroll
    for (int o = 16; o; o >>= 1) cnt += __shfl_xor_sync(FULL, cnt, o);
    if (lane == 0) s_cnt[wid] = cnt;
    __syncthreads();
    if (tid == 0) {
        int total = 0;
        #pragma unroll
        for (int i = 0; i < 8; i++) total += s_cnt[i];
        int loc = (total >= N_NEUR) ? 0 : total;   // argmax of all-false -> 0
        g_loc[t] = loc;
        const float logr = logf(rand_val[t]);
        const float thr  = ((logf(stot) + mp) + LOG_DT_F) - logr;
        g_thr[t] = thr;
        out[(size_t)T_STEPS * N_NEUR + T_STEPS + t] = c;   // noise output
    }

    // --- zero-fill the out_spikes row (scatter of 1.0s happens later) ---
    reinterpret_cast<float4*>(out)[(size_t)t * (N_NEUR / 4) + tid] =
        make_float4(0.0f, 0.0f, 0.0f, 0.0f);
}

// ---------------------------------------------------------------------------
// Serial inhibition recurrence (bit-faithful to the fp32 scan):
//   spike_t = inh_t < thr_t
//   inh_{t+1} = inh_t * F + (spike ? 3000 : 0)     [a + 0.0f == a exactly]
// Thread 0 scans a chunk from shared memory; the other threads stage thr in
// and write inhibition / scatter spikes out. Spike flag is recovered from
// inh >= 3000 (no-spike value <= ~2477, post-spike value >= 3000).
// ---------------------------------------------------------------------------
__global__ void __launch_bounds__(THREADS)
scan_kernel(float* __restrict__ out)
{
    __shared__ float s_thr[CHUNK];
    __shared__ float s_inh[CHUNK];
    const int tid = threadIdx.x;

    float v = 0.0f;   // only thread 0's copy matters
    for (int base = 0; base < T_STEPS; base += CHUNK) {
        for (int i = tid; i < CHUNK; i += THREADS)
            s_thr[i] = g_thr[base + i];
        __syncthreads();

        if (tid == 0) {
            float vv = v;
            #pragma unroll 8
            for (int i = 0; i < CHUNK; ++i) {
                const float th = s_thr[i];
                const float a  = vv * INH_FACTOR_F;
                vv = (vv < th) ? (a + INH_INC_F) : a;
                s_inh[i] = vv;
            }
            v = vv;
        }
        __syncthreads();

        for (int i = tid; i < CHUNK; i += THREADS) {
            const int   t   = base + i;
            const float inh = s_inh[i];
            out[(size_t)T_STEPS * N_NEUR + t] = inh;       // inhibition output
            if (inh >= INH_INC_F) {                        // spike occurred
                out[(size_t)t * N_NEUR + g_loc[t]] = 1.0f; // one-hot spike
            }
        }
        __syncthreads();
    }
}

extern "C" void kernel_launch(void* const* d_in, const int* in_sizes, int n_in,
                              void* d_out, int out_size)
{
    const float* inputs     = (const float*)d_in[0];
    const float* noise_rand = (const float*)d_in[1];
    const float* u_mult     = (const float*)d_in[2];
    const float* rand_val   = (const float*)d_in[3];
    float* out = (float*)d_out;

    row_kernel<<<T_STEPS, THREADS>>>(inputs, noise_rand, u_mult, rand_val, out);
    scan_kernel<<<1, THREADS>>>(out);
}

// round 5
// speedup vs baseline: 1.9391x; 1.9391x over previous
#include <cuda_runtime.h>
#include <math.h>

#define T_STEPS   32768
#define N_NEUR    1024
#define FILT_LEN  200
#define THREADS   256

#define LOG_DT_F      (-6.907755278982137f)
#define NOISE_SIGMA_F (0.2f)
#define FILT_DECAY_F  (0.05f)
#define INH_FACTOR_F  (0.8187307530779818f)
#define INH_INC_F     (3000.0f)

// scratch (no cudaMalloc allowed)
__device__ float g_thr[T_STEPS];
__device__ int   g_loc[T_STEPS];

// ---------------------------------------------------------------------------
// One block per time step t (unchanged from R3 — passes, ~70us, ~3.7TB/s).
// ---------------------------------------------------------------------------
__global__ void __launch_bounds__(THREADS)
row_kernel(const float* __restrict__ inputs,
           const float* __restrict__ noise_rand,
           const float* __restrict__ u_mult,
           const float* __restrict__ rand_val,
           float* __restrict__ out)
{
    const int t    = blockIdx.x;
    const int tid  = threadIdx.x;
    const int lane = tid & 31;
    const int wid  = tid >> 5;
    const unsigned FULL = 0xffffffffu;

    __shared__ float s_max[8];
    __shared__ float s_ns[8];
    __shared__ float s_wsum[8];
    __shared__ int   s_cnt[8];
    __shared__ float s_b[2];   // [0]=noise c, [1]=m' = rowmax + c

    const float4 x4 =
        reinterpret_cast<const float4*>(inputs)[(size_t)t * (N_NEUR / 4) + tid];

    // --- noise tap: noise[t] = sum_j nr[t-j] * exp(-j*0.05) ---
    float prod = 0.0f;
    if (tid < FILT_LEN) {
        int idx = t - tid;
        if (idx >= 0) {
            float nr   = noise_rand[idx] * NOISE_SIGMA_F;
            float filt = expf(-((float)tid) * FILT_DECAY_F);
            prod = nr * filt;
        }
    }

    // --- joint warp reduce: row max + noise sum ---
    float lm = fmaxf(fmaxf(x4.x, x4.y), fmaxf(x4.z, x4.w));
    #pragma unroll
    for (int o = 16; o; o >>= 1) {
        lm   = fmaxf(lm, __shfl_xor_sync(FULL, lm, o));
        prod += __shfl_xor_sync(FULL, prod, o);
    }
    if (lane == 0) { s_max[wid] = lm; s_ns[wid] = prod; }
    __syncthreads();
    if (tid == 0) {
        float m = s_max[0], c = s_ns[0];
        #pragma unroll
        for (int i = 1; i < 8; i++) { m = fmaxf(m, s_max[i]); c += s_ns[i]; }
        s_b[0] = c;
        s_b[1] = m + c;     // m' for inputs+noise (monotone rounding)
    }
    __syncthreads();
    const float c  = s_b[0];
    const float mp = s_b[1];

    const float e0 = expf((x4.x + c) - mp);
    const float e1 = expf((x4.y + c) - mp);
    const float e2 = expf((x4.z + c) - mp);
    const float e3 = expf((x4.w + c) - mp);
    const float p0 = e0;
    const float p1 = p0 + e1;
    const float p2 = p1 + e2;
    const float p3 = p2 + e3;

    float incl = p3;
    #pragma unroll
    for (int o = 1; o < 32; o <<= 1) {
        float n = __shfl_up_sync(FULL, incl, o);
        if (lane >= o) incl += n;
    }
    if (lane == 31) s_wsum[wid] = incl;
    __syncthreads();
    float warp_off = 0.0f, stot = 0.0f;
    {
        float acc = 0.0f;
        #pragma unroll
        for (int i = 0; i < 8; i++) {
            if (i == wid) warp_off = acc;
            acc += s_wsum[i];
        }
        stot = acc;
    }
    float excl = __shfl_up_sync(FULL, incl, 1);
    if (lane == 0) excl = 0.0f;
    const float base = warp_off + excl;

    const float us = u_mult[t] * stot;
    int cnt = (int)((base + p0) < us) + (int)((base + p1) < us)
            + (int)((base + p2) < us) + (int)((base + p3) < us);
    #pragma unroll
    for (int o = 16; o; o >>= 1) cnt += __shfl_xor_sync(FULL, cnt, o);
    if (lane == 0) s_cnt[wid] = cnt;
    __syncthreads();
    if (tid == 0) {
        int total = 0;
        #pragma unroll
        for (int i = 0; i < 8; i++) total += s_cnt[i];
        int loc = (total >= N_NEUR) ? 0 : total;
        g_loc[t] = loc;
        const float logr = logf(rand_val[t]);
        const float thr  = ((logf(stot) + mp) + LOG_DT_F) - logr;
        g_thr[t] = thr;
        out[(size_t)T_STEPS * N_NEUR + T_STEPS + t] = c;   // noise output
    }

    reinterpret_cast<float4*>(out)[(size_t)t * (N_NEUR / 4) + tid] =
        make_float4(0.0f, 0.0f, 0.0f, 0.0f);
}

// ---------------------------------------------------------------------------
// Speculative warp-parallel inhibition scan.
//
// Between spikes the recurrence is a pure multiply chain: v <- v*F (exact:
// reference adds literal 0.0f to a positive value). Spikes are rare (~1/40
// steps). Per round, each lane L runs a PREDICATED FMUL chain producing
// b = w_{L+1} = v after exactly L+1 sequential fp32 multiplies — bit-identical
// to the serial scan. One ballot over "w_L < thr[t+L]" finds the first spike
// j; rollback: v' = w_{j+1} + 3000 (same FMUL-then-FADD rounding as serial).
// All spike decisions are therefore bit-exact vs the serial recurrence.
//
// thr (fp32) + spike locations (u16) staged in 197KB dynamic shared memory so
// the loop never stalls on global loads.
// ---------------------------------------------------------------------------
__global__ void __launch_bounds__(THREADS)
scan_kernel(float* __restrict__ out)
{
    extern __shared__ char smem[];
    float*          s_thr = reinterpret_cast<float*>(smem);
    unsigned short* s_loc =
        reinterpret_cast<unsigned short*>(smem + (T_STEPS + 32) * sizeof(float));

    const int tid = threadIdx.x;

    // ---- stage thr + loc into shared (all 8 warps) ----
    for (int i = tid; i < T_STEPS; i += THREADS) {
        s_thr[i] = g_thr[i];
        s_loc[i] = (unsigned short)g_loc[i];
    }
    if (tid < 32) {
        s_thr[T_STEPS + tid] = __int_as_float(0xff800000);  // -inf: never spikes
        s_loc[T_STEPS + tid] = 0;
    }
    __syncthreads();

    if (tid >= 32) return;          // warp 0 only from here on
    const int lane = tid;
    const unsigned FULL = 0xffffffffu;
    const float F = INH_FACTOR_F;

    float v = 0.0f;
    int t = 0;
    while (t < T_STEPS) {
        const float thr = s_thr[t + lane];                 // LDS, off-chain
        const int   loc = (int)s_loc[t + lane];            // LDS, off-chain

        // Predicated FMUL chain: lane L ends with b = w_{L+1} (L+1 exact
        // sequential roundings). Inline asm forces @p FMUL (4 cyc/step)
        // instead of FMUL+FSEL (8 cyc/step).
        float b = v;
        #pragma unroll
        for (int i = 0; i < 32; ++i) {
            asm("{\n\t"
                ".reg .pred p;\n\t"
                "setp.ge.s32 p, %1, %2;\n\t"
                "@p mul.rn.f32 %0, %0, %3;\n\t"
                "}"
                : "+f"(b) : "r"(lane), "r"(i), "f"(F));
        }

        // w_L for lane L = lane (L-1)'s b ; lane 0 uses v itself.
        float w = __shfl_up_sync(FULL, b, 1);
        if (lane == 0) w = v;

        const unsigned mask = __ballot_sync(FULL, w < thr);
        const bool  spike = (mask != 0u);
        const int   j     = spike ? (__ffs(mask) - 1) : 31;

        const float wn = __shfl_sync(FULL, b, j);          // w_{j+1}
        const float vn = wn + (spike ? INH_INC_F : 0.0f);  // exact: +0.0 identity

        if (lane <= j && (t + lane) < T_STEPS) {
            // inhibition output at step t+L is w_{L+1} (+3000 on the spike step)
            out[(size_t)T_STEPS * N_NEUR + (t + lane)] = (lane == j) ? vn : b;
            if (spike && lane == j)
                out[(size_t)(t + lane) * N_NEUR + loc] = 1.0f;
        }

        v = vn;
        t += j + 1;
    }
}

extern "C" void kernel_launch(void* const* d_in, const int* in_sizes, int n_in,
                              void* d_out, int out_size)
{
    const float* inputs     = (const float*)d_in[0];
    const float* noise_rand = (const float*)d_in[1];
    const float* u_mult     = (const float*)d_in[2];
    const float* rand_val   = (const float*)d_in[3];
    float* out = (float*)d_out;

    const size_t smem_bytes =
        (size_t)(T_STEPS + 32) * sizeof(float) +
        (size_t)(T_STEPS + 32) * sizeof(unsigned short);

    static int configured = 0;
    if (!configured) {
        cudaFuncSetAttribute(scan_kernel,
                             cudaFuncAttributeMaxDynamicSharedMemorySize,
                             (int)smem_bytes);
        configured = 1;
    }

    row_kernel<<<T_STEPS, THREADS>>>(inputs, noise_rand, u_mult, rand_val, out);
    scan_kernel<<<1, THREADS, smem_bytes>>>(out);
}

// round 6
// speedup vs baseline: 4.1629x; 2.1468x over previous
#include <cuda_runtime.h>
#include <math.h>

#define T_STEPS   32768
#define N_NEUR    1024
#define FILT_LEN  200
#define THREADS   256
#define CHUNK     1024
#define NCH       (T_STEPS / CHUNK)
#define FCAP      1024            // F^k == 0 (fp32) for k >= ~516, so capping at 1024 is exact

#define LOG_DT_F      (-6.907755278982137f)
#define NOISE_SIGMA_F (0.2f)
#define FILT_DECAY_F  (0.05f)
#define INH_FACTOR_F  (0.8187307530779818f)
#define INH_INC_F     (3000.0f)

// scratch (no cudaMalloc allowed)
__device__ float          g_thr[T_STEPS];
__device__ unsigned short g_loc[T_STEPS];
__device__ int            g_cnt[NCH];      // per-chunk completion counters

__global__ void init_kernel() {
    if (threadIdx.x < NCH) g_cnt[threadIdx.x] = 0;
}

// ---------------------------------------------------------------------------
// Fused kernel. Block 0 = persistent scanner (scheduled first wave, always
// co-resident). Blocks 1..T_STEPS = one time-step row each (producer).
// Producers never wait on anything -> forward progress guaranteed.
// ---------------------------------------------------------------------------
__global__ void __launch_bounds__(THREADS)
fused_kernel(const float* __restrict__ inputs,
             const float* __restrict__ noise_rand,
             const float* __restrict__ u_mult,
             const float* __restrict__ rand_val,
             float* __restrict__ out)
{
    const int tid  = threadIdx.x;
    const int lane = tid & 31;
    const unsigned FULL = 0xffffffffu;
    const size_t IDX_INH = (size_t)T_STEPS * N_NEUR;

    // Scanner smem (allocated for all blocks; 16KB keeps 8 blocks/SM).
    __shared__ float          s_fp[FCAP + 1];
    __shared__ float          s_thr[2][CHUNK];
    __shared__ unsigned short s_loc[2][CHUNK];
    // Producer smem (reuses a different footprint; union not worth it)
    __shared__ float s_max[8];
    __shared__ float s_ns[8];
    __shared__ float s_wsum[8];
    __shared__ int   s_cnt[8];
    __shared__ float s_b[2];

    if (blockIdx.x != 0) {
        // =================== PRODUCER: row t = blockIdx.x - 1 ===============
        const int t   = blockIdx.x - 1;
        const int wid = tid >> 5;

        const float4 x4 =
            reinterpret_cast<const float4*>(inputs)[(size_t)t * (N_NEUR / 4) + tid];

        // noise tap: noise[t] = sum_j nr[t-j] * exp(-j*0.05)
        float prod = 0.0f;
        if (tid < FILT_LEN) {
            int idx = t - tid;
            if (idx >= 0) {
                float nr   = noise_rand[idx] * NOISE_SIGMA_F;
                float filt = expf(-((float)tid) * FILT_DECAY_F);
                prod = nr * filt;
            }
        }

        // joint warp reduce: row max + noise sum
        float lm = fmaxf(fmaxf(x4.x, x4.y), fmaxf(x4.z, x4.w));
        #pragma unroll
        for (int o = 16; o; o >>= 1) {
            lm   = fmaxf(lm, __shfl_xor_sync(FULL, lm, o));
            prod += __shfl_xor_sync(FULL, prod, o);
        }
        if (lane == 0) { s_max[wid] = lm; s_ns[wid] = prod; }
        __syncthreads();
        if (tid == 0) {
            float m = s_max[0], c = s_ns[0];
            #pragma unroll
            for (int i = 1; i < 8; i++) { m = fmaxf(m, s_max[i]); c += s_ns[i]; }
            s_b[0] = c;
            s_b[1] = m + c;     // m' for inputs+noise (monotone rounding)
        }
        __syncthreads();
        const float c  = s_b[0];
        const float mp = s_b[1];

        const float e0 = expf((x4.x + c) - mp);
        const float e1 = expf((x4.y + c) - mp);
        const float e2 = expf((x4.z + c) - mp);
        const float e3 = expf((x4.w + c) - mp);
        const float p0 = e0;
        const float p1 = p0 + e1;
        const float p2 = p1 + e2;
        const float p3 = p2 + e3;

        float incl = p3;
        #pragma unroll
        for (int o = 1; o < 32; o <<= 1) {
            float n = __shfl_up_sync(FULL, incl, o);
            if (lane >= o) incl += n;
        }
        if (lane == 31) s_wsum[wid] = incl;
        __syncthreads();
        float warp_off = 0.0f, stot = 0.0f;
        {
            float acc = 0.0f;
            #pragma unroll
            for (int i = 0; i < 8; i++) {
                if (i == wid) warp_off = acc;
                acc += s_wsum[i];
            }
            stot = acc;
        }
        float excl = __shfl_up_sync(FULL, incl, 1);
        if (lane == 0) excl = 0.0f;
        const float base = warp_off + excl;

        const float us = u_mult[t] * stot;
        int cnt = (int)((base + p0) < us) + (int)((base + p1) < us)
                + (int)((base + p2) < us) + (int)((base + p3) < us);
        #pragma unroll
        for (int o = 16; o; o >>= 1) cnt += __shfl_xor_sync(FULL, cnt, o);
        if (lane == 0) s_cnt[wid] = cnt;
        __syncthreads();
        if (tid == 0) {
            int total = 0;
            #pragma unroll
            for (int i = 0; i < 8; i++) total += s_cnt[i];
            int loc = (total >= N_NEUR) ? 0 : total;
            g_loc[t] = (unsigned short)loc;
            const float logr = logf(rand_val[t]);
            g_thr[t] = ((logf(stot) + mp) + LOG_DT_F) - logr;
            out[IDX_INH + T_STEPS + t] = c;    // noise output
        }

        // zero-fill the out_spikes row (scanner scatters rare 1.0s later)
        reinterpret_cast<float4*>(out)[(size_t)t * (N_NEUR / 4) + tid] =
            make_float4(0.0f, 0.0f, 0.0f, 0.0f);

        // release: all row data visible before the chunk counter bump
        __threadfence();
        __syncthreads();
        if (tid == 0) atomicAdd(&g_cnt[t >> 10], 1);
        return;
    }

    // ======================= SCANNER (block 0) ==============================
    // F^k table (double-accurate, single fp32 rounding); Fp[FCAP] = 0.
    for (int i = tid; i <= FCAP; i += THREADS)
        s_fp[i] = (i >= FCAP) ? 0.0f : (float)exp(-0.2 * (double)i);

    // stage chunk 0 (all 8 warps)
    while (*((volatile int*)&g_cnt[0]) < CHUNK) __nanosleep(128);
    __threadfence();   // acquire
    for (int i = tid; i < CHUNK; i += THREADS) {
        s_thr[0][i] = g_thr[i];
        s_loc[0][i] = g_loc[i];
    }
    __syncthreads();

    // Warp-0 scan state: between spikes v_t = A * F^k (closed form).
    float A = 0.0f;      // v at position p (exponent k): v_p = A*Fp[k]; A=0 start
    int   p = 0;         // next undecided step
    int   k = 0;         // decay exponent at p

    for (int ch = 0; ch < NCH; ++ch) {
        if (tid >= 32) {
            // warps 1..7: poll + stage next chunk into the other buffer
            const int cn = ch + 1;
            if (cn < NCH) {
                while (*((volatile int*)&g_cnt[cn]) < CHUNK) __nanosleep(128);
                __threadfence();   // acquire
                float*          dt = s_thr[cn & 1];
                unsigned short* dl = s_loc[cn & 1];
                const int off = cn * CHUNK;
                for (int i = tid - 32; i < CHUNK; i += THREADS - 32) {
                    dt[i] = g_thr[off + i];
                    dl[i] = g_loc[off + i];
                }
            }
        } else {
            // warp 0: scan chunk ch from smem
            const float*          thrb = s_thr[ch & 1];
            const unsigned short* locb = s_loc[ch & 1];
            const int cbase = ch * CHUNK;
            const int cend  = cbase + CHUNK;

            while (p < cend) {
                const int rem = cend - p;                 // >= 1
                const int l2  = lane << 1;
                const int i0  = (p - cbase) + l2;
                const bool ok0 = l2 < rem;
                const bool ok1 = (l2 + 1) < rem;

                const float thr0 = thrb[min(i0,     CHUNK - 1)];
                const float thr1 = thrb[min(i0 + 1, CHUNK - 1)];

                const float v0 = __fmul_rn(A, s_fp[min(k + l2,     FCAP)]);
                const float v1 = __fmul_rn(A, s_fp[min(k + l2 + 1, FCAP)]);
                const float v2 = __fmul_rn(A, s_fp[min(k + l2 + 2, FCAP)]);

                const unsigned m0 = __ballot_sync(FULL, ok0 && (v0 < thr0));
                const unsigned m1 = __ballot_sync(FULL, ok1 && (v1 < thr1));

                if (m0 | m1) {
                    const int j0 = m0 ? ((__ffs(m0) - 1) << 1)       : (1 << 30);
                    const int j1 = m1 ? (((__ffs(m1) - 1) << 1) | 1) : (1 << 30);
                    const int j  = min(j0, j1);          // first spike offset

                    const float vj = __fmul_rn(A, s_fp[min(k + j, FCAP)]);
                    const float An = __fadd_rn(__fmul_rn(vj, INH_FACTOR_F), INH_INC_F);

                    // inhibition[t] = v_{t+1}: A*Fp[k+off+1], An at the spike step
                    if (l2 <= j)
                        out[IDX_INH + (p + l2)]     = (l2 == j)     ? An : v1;
                    if (l2 + 1 <= j)
                        out[IDX_INH + (p + l2 + 1)] = (l2 + 1 == j) ? An : v2;
                    if (lane == (j >> 1)) {
                        const int ts = p + j;
                        out[(size_t)ts * N_NEUR + (int)locb[ts - cbase]] = 1.0f;
                    }
                    A = An; p += j + 1; k = 0;
                } else {
                    const int W = min(64, rem);
                    if (ok0) out[IDX_INH + (p + l2)]     = v1;
                    if (ok1) out[IDX_INH + (p + l2 + 1)] = v2;
                    p += W; k += W;
                }
            }
        }
        __syncthreads();
    }
}

extern "C" void kernel_launch(void* const* d_in, const int* in_sizes, int n_in,
                              void* d_out, int out_size)
{
    const float* inputs     = (const float*)d_in[0];
    const float* noise_rand = (const float*)d_in[1];
    const float* u_mult     = (const float*)d_in[2];
    const float* rand_val   = (const float*)d_in[3];
    float* out = (float*)d_out;

    init_kernel<<<1, 32>>>();
    fused_kernel<<<T_STEPS + 1, THREADS>>>(inputs, noise_rand, u_mult, rand_val, out);
}

// round 7
// speedup vs baseline: 4.2030x; 1.0096x over previous
#include <cuda_runtime.h>
#include <math.h>

#define T_STEPS   32768
#define N_NEUR    1024
#define FILT_LEN  200
#define THREADS   256
#define CHUNK     1024
#define NCH       (T_STEPS / CHUNK)
#define FCAP      1024            // F^k == 0 (fp32) well before k=1024

#define LOG_DT_F      (-6.907755278982137f)
#define NOISE_SIGMA_F (0.2f)
#define FILT_DECAY_F  (0.05f)
#define INH_FACTOR_F  (0.8187307530779818f)
#define INH_INC_F     (3000.0f)

// scratch (no cudaMalloc allowed)
__device__ float          g_thr[T_STEPS];
__device__ unsigned short g_loc[T_STEPS];
__device__ int            g_cnt[NCH * 32];   // padded: one counter per 128B line

__global__ void init_kernel() {
    g_cnt[threadIdx.x] = 0;                  // 1024 threads zero NCH*32 ints
}

// ---------------------------------------------------------------------------
// Fused kernel. Block 0 = persistent scanner (first wave, always co-resident).
// Blocks 1..T_STEPS = one time-step row each (producer). Producers never wait
// on anything -> forward progress guaranteed.
//
// R6 change: per-block release is ONE thread's fence+atomic after the CTA
// barrier (CTA barrier chains all threads' stores into tid0's cumulative
// gpu-scope fence); counters padded to 128B stride; scanner polls from one
// lane per warp only.
// ---------------------------------------------------------------------------
__global__ void __launch_bounds__(THREADS)
fused_kernel(const float* __restrict__ inputs,
             const float* __restrict__ noise_rand,
             const float* __restrict__ u_mult,
             const float* __restrict__ rand_val,
             float* __restrict__ out)
{
    const int tid  = threadIdx.x;
    const int lane = tid & 31;
    const unsigned FULL = 0xffffffffu;
    const size_t IDX_INH = (size_t)T_STEPS * N_NEUR;

    __shared__ float          s_fp[FCAP + 1];
    __shared__ float          s_thr[2][CHUNK];
    __shared__ unsigned short s_loc[2][CHUNK];
    __shared__ float s_max[8];
    __shared__ float s_ns[8];
    __shared__ float s_wsum[8];
    __shared__ int   s_cnt[8];
    __shared__ float s_b[2];

    if (blockIdx.x != 0) {
        // =================== PRODUCER: row t = blockIdx.x - 1 ===============
        const int t   = blockIdx.x - 1;
        const int wid = tid >> 5;

        const float4 x4 =
            reinterpret_cast<const float4*>(inputs)[(size_t)t * (N_NEUR / 4) + tid];

        // noise tap: noise[t] = sum_j nr[t-j] * exp(-j*0.05)
        float prod = 0.0f;
        if (tid < FILT_LEN) {
            int idx = t - tid;
            if (idx >= 0) {
                float nr   = noise_rand[idx] * NOISE_SIGMA_F;
                float filt = expf(-((float)tid) * FILT_DECAY_F);
                prod = nr * filt;
            }
        }

        // joint warp reduce: row max + noise sum
        float lm = fmaxf(fmaxf(x4.x, x4.y), fmaxf(x4.z, x4.w));
        #pragma unroll
        for (int o = 16; o; o >>= 1) {
            lm   = fmaxf(lm, __shfl_xor_sync(FULL, lm, o));
            prod += __shfl_xor_sync(FULL, prod, o);
        }
        if (lane == 0) { s_max[wid] = lm; s_ns[wid] = prod; }
        __syncthreads();
        if (tid == 0) {
            float m = s_max[0], c = s_ns[0];
            #pragma unroll
            for (int i = 1; i < 8; i++) { m = fmaxf(m, s_max[i]); c += s_ns[i]; }
            s_b[0] = c;
            s_b[1] = m + c;     // m' for inputs+noise (monotone rounding)
        }
        __syncthreads();
        const float c  = s_b[0];
        const float mp = s_b[1];

        const float e0 = expf((x4.x + c) - mp);
        const float e1 = expf((x4.y + c) - mp);
        const float e2 = expf((x4.z + c) - mp);
        const float e3 = expf((x4.w + c) - mp);
        const float p0 = e0;
        const float p1 = p0 + e1;
        const float p2 = p1 + e2;
        const float p3 = p2 + e3;

        float incl = p3;
        #pragma unroll
        for (int o = 1; o < 32; o <<= 1) {
            float n = __shfl_up_sync(FULL, incl, o);
            if (lane >= o) incl += n;
        }
        if (lane == 31) s_wsum[wid] = incl;
        __syncthreads();
        float warp_off = 0.0f, stot = 0.0f;
        {
            float acc = 0.0f;
            #pragma unroll
            for (int i = 0; i < 8; i++) {
                if (i == wid) warp_off = acc;
                acc += s_wsum[i];
            }
            stot = acc;
        }
        float excl = __shfl_up_sync(FULL, incl, 1);
        if (lane == 0) excl = 0.0f;
        const float base = warp_off + excl;

        const float us = u_mult[t] * stot;
        int cnt = (int)((base + p0) < us) + (int)((base + p1) < us)
                + (int)((base + p2) < us) + (int)((base + p3) < us);
        #pragma unroll
        for (int o = 16; o; o >>= 1) cnt += __shfl_xor_sync(FULL, cnt, o);
        if (lane == 0) s_cnt[wid] = cnt;
        __syncthreads();
        if (tid == 0) {
            int total = 0;
            #pragma unroll
            for (int i = 0; i < 8; i++) total += s_cnt[i];
            int loc = (total >= N_NEUR) ? 0 : total;
            g_loc[t] = (unsigned short)loc;
            const float logr = logf(rand_val[t]);
            g_thr[t] = ((logf(stot) + mp) + LOG_DT_F) - logr;
            out[IDX_INH + T_STEPS + t] = c;    // noise output
        }

        // zero-fill the out_spikes row (scanner scatters rare 1.0s later)
        reinterpret_cast<float4*>(out)[(size_t)t * (N_NEUR / 4) + tid] =
            make_float4(0.0f, 0.0f, 0.0f, 0.0f);

        // release: CTA barrier chains all threads' stores into tid0's
        // cumulative gpu-scope fence; ONE fence + ONE atomic per block.
        __syncthreads();
        if (tid == 0) {
            __threadfence();
            atomicAdd(&g_cnt[(t >> 10) << 5], 1);
        }
        return;
    }

    // ======================= SCANNER (block 0) ==============================
    for (int i = tid; i <= FCAP; i += THREADS)
        s_fp[i] = (i >= FCAP) ? 0.0f : (float)exp(-0.2 * (double)i);

    // stage chunk 0 (all 8 warps); one thread polls
    if (tid == 0) {
        while (*((volatile int*)&g_cnt[0]) < CHUNK) __nanosleep(256);
        __threadfence();   // acquire
    }
    __syncthreads();
    for (int i = tid; i < CHUNK; i += THREADS) {
        s_thr[0][i] = g_thr[i];
        s_loc[0][i] = g_loc[i];
    }
    __syncthreads();

    // Warp-0 scan state: between spikes v_t = A * F^k (closed form).
    float A = 0.0f;
    int   p = 0;
    int   k = 0;

    for (int ch = 0; ch < NCH; ++ch) {
        if (tid >= 32) {
            // warps 1..7: poll (lane 0 only) + stage next chunk
            const int cn = ch + 1;
            if (cn < NCH) {
                if (lane == 0) {
                    while (*((volatile int*)&g_cnt[cn << 5]) < CHUNK)
                        __nanosleep(256);
                    __threadfence();   // acquire
                }
                __syncwarp();
                float*          dt = s_thr[cn & 1];
                unsigned short* dl = s_loc[cn & 1];
                const int off = cn * CHUNK;
                for (int i = tid - 32; i < CHUNK; i += THREADS - 32) {
                    dt[i] = g_thr[off + i];
                    dl[i] = g_loc[off + i];
                }
            }
        } else {
            // warp 0: scan chunk ch from smem
            const float*          thrb = s_thr[ch & 1];
            const unsigned short* locb = s_loc[ch & 1];
            const int cbase = ch * CHUNK;
            const int cend  = cbase + CHUNK;

            while (p < cend) {
                const int rem = cend - p;                 // >= 1
                const int l2  = lane << 1;
                const int i0  = (p - cbase) + l2;
                const bool ok0 = l2 < rem;
                const bool ok1 = (l2 + 1) < rem;

                const float thr0 = thrb[min(i0,     CHUNK - 1)];
                const float thr1 = thrb[min(i0 + 1, CHUNK - 1)];

                const float v0 = __fmul_rn(A, s_fp[min(k + l2,     FCAP)]);
                const float v1 = __fmul_rn(A, s_fp[min(k + l2 + 1, FCAP)]);
                const float v2 = __fmul_rn(A, s_fp[min(k + l2 + 2, FCAP)]);

                const unsigned m0 = __ballot_sync(FULL, ok0 && (v0 < thr0));
                const unsigned m1 = __ballot_sync(FULL, ok1 && (v1 < thr1));

                if (m0 | m1) {
                    const int j0 = m0 ? ((__ffs(m0) - 1) << 1)       : (1 << 30);
                    const int j1 = m1 ? (((__ffs(m1) - 1) << 1) | 1) : (1 << 30);
                    const int j  = min(j0, j1);          // first spike offset

                    const float vj = __fmul_rn(A, s_fp[min(k + j, FCAP)]);
                    const float An = __fadd_rn(__fmul_rn(vj, INH_FACTOR_F), INH_INC_F);

                    if (l2 <= j)
                        out[IDX_INH + (p + l2)]     = (l2 == j)     ? An : v1;
                    if (l2 + 1 <= j)
                        out[IDX_INH + (p + l2 + 1)] = (l2 + 1 == j) ? An : v2;
                    if (lane == (j >> 1)) {
                        const int ts = p + j;
                        out[(size_t)ts * N_NEUR + (int)locb[ts - cbase]] = 1.0f;
                    }
                    A = An; p += j + 1; k = 0;
                } else {
                    const int W = min(64, rem);
                    if (ok0) out[IDX_INH + (p + l2)]     = v1;
                    if (ok1) out[IDX_INH + (p + l2 + 1)] = v2;
                    p += W; k += W;
                }
            }
        }
        __syncthreads();
    }
}

extern "C" void kernel_launch(void* const* d_in, const int* in_sizes, int n_in,
                              void* d_out, int out_size)
{
    const float* inputs     = (const float*)d_in[0];
    const float* noise_rand = (const float*)d_in[1];
    const float* u_mult     = (const float*)d_in[2];
    const float* rand_val   = (const float*)d_in[3];
    float* out = (float*)d_out;

    init_kernel<<<1, NCH * 32>>>();
    fused_kernel<<<T_STEPS + 1, THREADS>>>(inputs, noise_rand, u_mult, rand_val, out);
}